// round 17
// baseline (speedup 1.0000x reference)
#include <cuda_runtime.h>
#include <float.h>
#include <math.h>

// Problem constants
#define BATCH 2
#define NPT   64      // user inputs per batch
#define CCH   256     // feature channels
#define KCLS  10      // classes
#define KT    32      // K-tile per pipeline stage (k_cor)

// Scratch (device globals; no allocation allowed)
__device__ float g_tmplT[3 * BATCH * CCH * NPT];      // template [lvl][b][c][n]
__device__ float g_pcor[2 * BATCH * NPT * 5376];      // c-split partial correlations
__device__ int   g_order[BATCH * NPT];                // n indices grouped by class
__device__ int   g_start[BATCH * 12];                 // group boundaries per batch

// int64-vs-int32 detection: labels in [1,10]; if int64 LE, word 1 == high(label0) == 0.
__device__ __forceinline__ bool detect64(const int* labels_i32) {
    return labels_i32[1] == 0;
}
__device__ __forceinline__ int geti(const int* p, int i, bool is64) {
    return p[is64 ? 2 * i : i];
}

// cp.async helpers
__device__ __forceinline__ void cp_async16(void* smem_dst, const void* gsrc) {
    unsigned s = (unsigned)__cvta_generic_to_shared(smem_dst);
    asm volatile("cp.async.cg.shared.global [%0], [%1], 16;\n" :: "r"(s), "l"(gsrc));
}
__device__ __forceinline__ void cp_commit() {
    asm volatile("cp.async.commit_group;\n" ::: "memory");
}
__device__ __forceinline__ void cp_wait1() {
    asm volatile("cp.async.wait_group 1;\n" ::: "memory");
}
__device__ __forceinline__ void cp_wait0() {
    asm volatile("cp.async.wait_group 0;\n" ::: "memory");
}

// ---------------------------------------------------------------------------
// K1: windowed template. grid 384 = 3 lvl x 2 b x 64 n, 256 thr (= channels).
// The Gaussian (sigma=3 image px) at level scale 8/16/32 has support of only
// R=3/2/1 level-pixels around the center: weights beyond the window are
// exp(-44)/exp(-88)/exp(-128) relative -- identically negligible. The
// normalization Sx*Sy is still the FULL-grid sum (matches reference).
// T[n][c] = sum_{p in window} w[p] * feat[c][p], written straight to g_tmplT.
// Blocks (lvl2, n==0) also compute the label grouping in parallel.
// ---------------------------------------------------------------------------
__global__ void __launch_bounds__(256) k_tmpl(
                       const float* __restrict__ x0,
                       const float* __restrict__ x1,
                       const float* __restrict__ x2,
                       const float* __restrict__ centers,
                       const int* __restrict__ idx_i32,
                       const int* __restrict__ labels_i32) {
    __shared__ float redx[64], redy[64];
    __shared__ float sW[49];
    __shared__ int sOff[49];
    __shared__ float sScale[1];
    __shared__ int sWin[5];          // xlo, nx, ylo, ny, nw
    __shared__ int slab[64];

    int blk = blockIdx.x;
    int level = blk >> 7;
    int rem = blk & 127;
    int b = rem >> 6, n = rem & 63;

    int hd = 64 >> level;
    int scale = 8 << level;
    int HW = hd * hd;
    int R = (level == 0) ? 3 : (level == 1) ? 2 : 1;
    int tid = threadIdx.x;
    bool is64 = detect64(labels_i32);
    const float alpha = -0.5f / 9.0f;   // sigma = 3

    // ---- label grouping (parallel, block-uniform branch; 2 tiny blocks) ----
    if (level == 2 && n == 0) {
        if (tid < 64) slab[tid] = geti(labels_i32, b * NPT + tid, is64);
        __syncthreads();
        if (tid < 64) {
            int myl = slab[tid];
            int rank = 0, base = 0;
            for (int m = 0; m < NPT; m++) {
                int lm = slab[m];
                rank += (m < tid && lm == myl) ? 1 : 0;
                base += (lm < myl) ? 1 : 0;
            }
            g_order[b * NPT + base + rank] = tid;
            if (tid <= KCLS) {
                int st = 0;
                for (int m = 0; m < NPT; m++)
                    st += (slab[m] < tid + 1) ? 1 : 0;
                g_start[b * 12 + tid] = st;
            }
        }
        __syncthreads();
    }

    float cx = centers[(b * NPT + n) * 2 + 0];
    float cy = centers[(b * NPT + n) * 2 + 1];

    // ---- full-grid separable sums Sx, Sy ----
    if (tid < 64) {
        float exv = 0.f, eyv = 0.f;
        if (tid < hd) {
            float coord = tid * (float)scale + 0.5f;
            float dx = coord - cx, dy = coord - cy;
            exv = __expf(alpha * dx * dx);
            eyv = __expf(alpha * dy * dy);
        }
        redx[tid] = exv; redy[tid] = eyv;
    }
    __syncthreads();
    for (int s = 32; s > 0; s >>= 1) {
        if (tid < s) { redx[tid] += redx[tid + s]; redy[tid] += redy[tid + s]; }
        __syncthreads();
    }

    // ---- window + scale ----
    if (tid == 0) {
        bool valid = geti(idx_i32, b * NPT + n, is64) != -1;
        sScale[0] = valid ? 1.0f / (redx[0] * redy[0] + 1e-8f) : 0.f;
        int pxc = (int)floorf((cx - 0.5f) / (float)scale + 0.5f);
        int pyc = (int)floorf((cy - 0.5f) / (float)scale + 0.5f);
        int xlo = max(0, pxc - R), xhi = min(hd - 1, pxc + R);
        int ylo = max(0, pyc - R), yhi = min(hd - 1, pyc + R);
        sWin[0] = xlo; sWin[1] = xhi - xlo + 1;
        sWin[2] = ylo; sWin[3] = yhi - ylo + 1;
        sWin[4] = sWin[1] * sWin[3];
    }
    __syncthreads();

    int nw = sWin[4], nx = sWin[1];
    if (tid < nw) {
        int wy = tid / nx, wx = tid - wy * nx;
        int x = sWin[0] + wx, y = sWin[2] + wy;
        float dx = x * (float)scale + 0.5f - cx;
        float dy = y * (float)scale + 0.5f - cy;
        sW[tid] = sScale[0] * __expf(alpha * dx * dx) * __expf(alpha * dy * dy);
        sOff[tid] = y * hd + x;
    }
    __syncthreads();

    // ---- gather: each thread = one channel ----
    const float* feat = (level == 0) ? x0 : (level == 1) ? x1 : x2;
    const float* fb = feat + (size_t)(b * CCH + tid) * HW;
    float acc = 0.f;
    int t2 = 0;
    for (; t2 + 4 <= nw; t2 += 4) {
        float v0 = fb[sOff[t2]]     * sW[t2];
        float v1 = fb[sOff[t2 + 1]] * sW[t2 + 1];
        float v2 = fb[sOff[t2 + 2]] * sW[t2 + 2];
        float v3 = fb[sOff[t2 + 3]] * sW[t2 + 3];
        acc += (v0 + v1) + (v2 + v3);
    }
    for (; t2 < nw; t2++)
        acc += fb[sOff[t2]] * sW[t2];

    g_tmplT[level * (BATCH * CCH * NPT) + (b * CCH + tid) * NPT + n] = acc;
}

// ---------------------------------------------------------------------------
// K2: correlation as cp.async GEMM, c-split by 2 (2-stage pipeline).
// Block 128 thr (4 warps), tile 32n(half) x 64px, K=128 (split) in 4 stages.
// Per k: 2 LDS.128 + 1 LDS.64 + 16 FFMA (84% density). Partial cor -> g_pcor.
// half==0 blocks copy their split's 128 feat channels from staged sB.
// grid 672: lvl0 512 (64 tiles x 2half x 2b x 2split), lvl1 128, lvl2 32.
// ---------------------------------------------------------------------------
__global__ void __launch_bounds__(128) k_cor(
                      const float* __restrict__ x0,
                      const float* __restrict__ x1,
                      const float* __restrict__ x2,
                      float* __restrict__ out) {
    __shared__ float sA[2][KT][32];   // [buf][k=c][n_local]
    __shared__ float sB[2][KT][64];   // [buf][k=c][px]

    int blk = blockIdx.x;
    int level, lb;
    if (blk < 512)      { level = 0; lb = blk; }
    else if (blk < 640) { level = 1; lb = blk - 512; }
    else                { level = 2; lb = blk - 640; }

    int split = lb & 1;
    int b = (lb >> 1) & 1;
    int half = (lb >> 2) & 1;
    int tile = lb >> 3;
    int HW = 4096 >> (2 * level);
    int px0 = tile * 64;
    int oOff = (level == 0) ? 0 : (level == 1) ? 2179072 : 2723840;
    int q5376 = (level == 0) ? 0 : (level == 1) ? 4096 : 5120;
    const float* feat = (level == 0) ? x0 : (level == 1) ? x1 : x2;

    int tid = threadIdx.x;
    int lane = tid & 31;
    int w = tid >> 5;

    const float* tsrc = g_tmplT + level * (BATCH * CCH * NPT) + (size_t)b * CCH * NPT
                        + (size_t)(split * 128) * NPT + half * 32;
    const float* fbase = feat + (size_t)(b * CCH + split * 128) * HW + px0;
    float* obase = out + oOff + (size_t)(b * (CCH + KCLS) + split * 128) * HW + px0;

    // sA: 256 f4/stage (2/thread); sB: 512 f4/stage (4/thread)
#define STAGE_CP(bufi, c0base)                                                    \
    {                                                                             \
        _Pragma("unroll")                                                         \
        for (int j = 0; j < 2; j++) {                                             \
            int idx = tid + j * 128;                                              \
            int r = idx >> 3, cq = (idx & 7) * 4;                                 \
            cp_async16(&sA[bufi][r][cq], tsrc + (size_t)((c0base) + r) * NPT + cq);\
        }                                                                         \
        _Pragma("unroll")                                                         \
        for (int j = 0; j < 4; j++) {                                             \
            int idx = tid + j * 128;                                              \
            int r = idx >> 4, cc = (idx & 15) * 4;                                \
            cp_async16(&sB[bufi][r][cc], fbase + (size_t)((c0base) + r) * HW + cc);\
        }                                                                         \
        cp_commit();                                                              \
    }

    STAGE_CP(0, 0);

    float accA[8], accB[8];
#pragma unroll
    for (int i = 0; i < 8; i++) { accA[i] = 0.f; accB[i] = 0.f; }

    int nw0 = w * 8;

    for (int kt = 0; kt < 128 / KT; kt++) {
        int buf = kt & 1;
        if (kt < 128 / KT - 1) {
            STAGE_CP(buf ^ 1, (kt + 1) * KT);
            cp_wait1();
        } else {
            cp_wait0();
        }
        __syncthreads();

#pragma unroll
        for (int k = 0; k < KT; k++) {
            float2 bv = *(const float2*)&sB[buf][k][lane * 2];
            float4 a0 = *(const float4*)&sA[buf][k][nw0];
            float4 a1 = *(const float4*)&sA[buf][k][nw0 + 4];
            accA[0] += a0.x * bv.x;  accB[0] += a0.x * bv.y;
            accA[1] += a0.y * bv.x;  accB[1] += a0.y * bv.y;
            accA[2] += a0.z * bv.x;  accB[2] += a0.z * bv.y;
            accA[3] += a0.w * bv.x;  accB[3] += a0.w * bv.y;
            accA[4] += a1.x * bv.x;  accB[4] += a1.x * bv.y;
            accA[5] += a1.y * bv.x;  accB[5] += a1.y * bv.y;
            accA[6] += a1.z * bv.x;  accB[6] += a1.z * bv.y;
            accA[7] += a1.w * bv.x;  accB[7] += a1.w * bv.y;
        }

        if (half == 0) {
            int c0 = kt * KT;
#pragma unroll
            for (int j = 0; j < 4; j++) {
                int idx = tid + j * 128;
                int r = idx >> 4, cc = (idx & 15) * 4;
                float4 v = *(const float4*)&sB[buf][r][cc];
                *(float4*)&obase[(size_t)(c0 + r) * HW + cc] = v;
            }
        }
        __syncthreads();
    }
#undef STAGE_CP

    // write partial correlations: g_pcor[(split*B+b)][n][q]
    float* pc = g_pcor + ((size_t)(split * BATCH + b) * NPT) * 5376
                + q5376 + px0 + lane * 2;
#pragma unroll
    for (int j = 0; j < 8; j++) {
        int n = half * 32 + nw0 + j;
        *(float2*)&pc[(size_t)n * 5376] = make_float2(accA[j], accB[j]);
    }
}

// ---------------------------------------------------------------------------
// K3: sum c-split partials + per-class max, one thread per (b,k,q) output,
// 4x-unrolled group loop for MLP.
// ---------------------------------------------------------------------------
__global__ void __launch_bounds__(256) k_fin(float* __restrict__ out) {
    __shared__ int s_order[BATCH * NPT];
    __shared__ int s_start[BATCH * 12];

    int tid = threadIdx.x;
    if (tid < BATCH * NPT) s_order[tid] = g_order[tid];
    if (tid < BATCH * 12) s_start[tid] = g_start[tid];
    __syncthreads();

    int t = blockIdx.x * 256 + tid;
    if (t >= BATCH * KCLS * 5376) return;
    int q = t % 5376;
    int rest = t / 5376;
    int k = rest % KCLS;
    int b = rest / KCLS;

    const float* pc0 = g_pcor + ((size_t)(0 * BATCH + b) * NPT) * 5376 + q;
    const float* pc1 = g_pcor + ((size_t)(1 * BATCH + b) * NPT) * 5376 + q;
    const int* so = s_order + b * NPT;

    int i0 = s_start[b * 12 + k], i1 = s_start[b * 12 + k + 1];
    float m = -FLT_MAX;
    int i = i0;
    for (; i + 4 <= i1; i += 4) {
        int n0 = so[i], n1 = so[i + 1], n2 = so[i + 2], n3 = so[i + 3];
        float a0 = pc0[(size_t)n0 * 5376], b0 = pc1[(size_t)n0 * 5376];
        float a1 = pc0[(size_t)n1 * 5376], b1 = pc1[(size_t)n1 * 5376];
        float a2 = pc0[(size_t)n2 * 5376], b2 = pc1[(size_t)n2 * 5376];
        float a3 = pc0[(size_t)n3 * 5376], b3 = pc1[(size_t)n3 * 5376];
        float v0 = a0 + b0, v1 = a1 + b1, v2 = a2 + b2, v3 = a3 + b3;
        m = fmaxf(m, fmaxf(fmaxf(v0, v1), fmaxf(v2, v3)));
    }
    for (; i < i1; i++) {
        int n = so[i];
        m = fmaxf(m, pc0[(size_t)n * 5376] + pc1[(size_t)n * 5376]);
    }
    if (i0 == i1) m = 0.f;

    int HW, hw, oOff;
    if (q < 4096)      { HW = 4096; hw = q;        oOff = 0; }
    else if (q < 5120) { HW = 1024; hw = q - 4096; oOff = 2179072; }
    else               { HW = 256;  hw = q - 5120; oOff = 2723840; }

    out[oOff + (size_t)(b * (CCH + KCLS) + CCH + k) * HW + hw] = m;
}

// ---------------------------------------------------------------------------
extern "C" void kernel_launch(void* const* d_in, const int* in_sizes, int n_in,
                              void* d_out, int out_size) {
    (void)in_sizes; (void)n_in; (void)out_size;
    const float* x0      = (const float*)d_in[0];
    const float* x1      = (const float*)d_in[1];
    const float* x2      = (const float*)d_in[2];
    const float* centers = (const float*)d_in[3];
    const int*   idx     = (const int*)d_in[4];
    const int*   labels  = (const int*)d_in[5];
    float* out = (float*)d_out;

    k_tmpl<<<384, 256>>>(x0, x1, x2, centers, idx, labels);
    k_cor<<<672, 128>>>(x0, x1, x2, out);
    k_fin<<<420, 256>>>(out);
}